// round 8
// baseline (speedup 1.0000x reference)
#include <cuda_runtime.h>
#include <math.h>

#define NG   4
#define NT   4096
#define ND   2048
#define NE   64
#define CAP  128
#define GT   (NG*NT)            // 16384
static const long long GTEC = (long long)GT * NE * CAP;   // 134217728

#define GEMM_BLOCKS 128         // <=148 -> all co-resident, spin-safe
#define ZERO_BLOCKS 1920
#define ROWF  (NE*CAP)          // 8192 floats per output row

// ---------------- scratch (device globals; no allocation) ----------------
__device__ float          d_gate1[GT];
__device__ float          d_gate2[GT];
__device__ int            d_e12[GT];        // e1 | (e2<<8)
__device__ unsigned char  d_se0[GT];        // sorted-order top-1 expert id
__device__ unsigned char  d_se1[GT];        // sorted-order top-2 expert id
__device__ unsigned short d_stok[GT];       // sorted-order token id
__device__ short          d_pos1[GT];       // capacity position of top-1
__device__ short          d_pos2[GT];       // capacity position of top-2
__device__ float          d_sumprob[NG*NE];
__device__ float          d_cnt[NG*NE];
__device__ float          d_zsum;
__device__ int            d_gemm_done;
__device__ int            d_sort_done;

// ---------------- f32x2 packed helpers ----------------
#define FMA_X2(d,a,b,c) asm("fma.rn.f32x2 %0, %1, %2, %3;" : "=l"(d) : "l"(a), "l"(b), "l"(c))
#define ADD_X2(d,a,b)   asm("add.rn.f32x2 %0, %1, %2;"     : "=l"(d) : "l"(a), "l"(b))
#define UNPK_X2(lo,hi,v) asm("mov.b64 {%0,%1}, %2;" : "=r"(lo), "=r"(hi) : "l"(v))

// ---------------- shared-memory union (static, < 48 KB) ----------------
struct GemmSmem {
    float sA2[32][132];
    float sB[32][64];
    float sL[64][65];
    float sInv[64];
    float sZ[64];
    int   sCnt[64];
};
struct PosSmem {
    unsigned char  s0[NT];
    unsigned char  s1[NT];
    unsigned short stk[NT];
    int segc[16];
    int segb[16];
};
union FusedSmem {
    GemmSmem g;
    unsigned long long sk[NT];   // 32 KB sort keys
    PosSmem p;
};

// ---------------- init accumulators ----------------
__global__ void init_accum() {
    int t = threadIdx.x;
    if (t < NG*NE) { d_sumprob[t] = 0.f; d_cnt[t] = 0.f; }
    if (t == 0) { d_zsum = 0.f; d_gemm_done = 0; d_sort_done = 0; }
}

// ---------------- fused mega-kernel ----------------
// blocks [0,128): GEMM (2 tiles) -> [0,4): group sort -> all: capacity positions
// blocks [128, 128+ZERO_BLOCKS): stream zeros over the 1.07 GB output
__global__ void __launch_bounds__(256) fused_all(
    const float* __restrict__ A,   // [GT][ND]
    const float* __restrict__ Wm,  // [ND][NE]
    const float* __restrict__ bias,// [NE]
    float* __restrict__ out
) {
    const int tid = threadIdx.x;

    // =============== zero path ===============
    if (blockIdx.x >= GEMM_BLOCKS) {
        const size_t n4 = (size_t)(2 * GTEC) / 4;
        const size_t stride = (size_t)ZERO_BLOCKS * 256;
        float4* o4 = (float4*)out;
        const float4 z = make_float4(0.f, 0.f, 0.f, 0.f);
        for (size_t i = (size_t)(blockIdx.x - GEMM_BLOCKS) * 256 + tid; i < n4; i += stride)
            __stwt(o4 + i, z);
        return;
    }

    __shared__ FusedSmem sm;

    // =============== phase 1: GEMM, 2 tiles of 64 rows ===============
    const int tr = tid >> 4;     // 0..15
    const int tc = tid & 15;     // 0..15

    unsigned long long m1;       // packed (-1,-1)
    asm("mov.b64 %0, {%1,%2};" : "=l"(m1) : "r"(__float_as_uint(-1.0f)), "r"(__float_as_uint(-1.0f)));

    for (int tile = 0; tile < 2; tile++) {
        const int row0 = blockIdx.x * 128 + tile * 64;

        unsigned long long sum[4][2], comp[4][2];
#pragma unroll
        for (int i = 0; i < 4; i++)
#pragma unroll
            for (int p = 0; p < 2; p++) { sum[i][p] = 0ull; comp[i][p] = 0ull; }

        for (int d0 = 0; d0 < ND; d0 += 32) {
#pragma unroll
            for (int it = 0; it < 2; it++) {
                int idx = tid + it * 256;          // 0..511
                int r   = idx >> 3;
                int c4  = (idx & 7) << 2;
                float4 v = *(const float4*)(A + (size_t)(row0 + r) * ND + d0 + c4);
                *(float2*)&sm.g.sA2[c4+0][2*r] = make_float2(v.x, v.x);
                *(float2*)&sm.g.sA2[c4+1][2*r] = make_float2(v.y, v.y);
                *(float2*)&sm.g.sA2[c4+2][2*r] = make_float2(v.z, v.z);
                *(float2*)&sm.g.sA2[c4+3][2*r] = make_float2(v.w, v.w);
            }
#pragma unroll
            for (int it = 0; it < 2; it++) {
                int idx = tid + it * 256;
                int r   = idx >> 4;
                int c4  = (idx & 15) << 2;
                *(float4*)&sm.g.sB[r][c4] = *(const float4*)(Wm + (size_t)(d0 + r) * NE + c4);
            }
            __syncthreads();

            unsigned long long ch[4][2];
#pragma unroll
            for (int i = 0; i < 4; i++)
#pragma unroll
                for (int p = 0; p < 2; p++) ch[i][p] = 0ull;

#pragma unroll
            for (int kk = 0; kk < 32; kk++) {
                const unsigned long long* ap = (const unsigned long long*)&sm.g.sA2[kk][8*tr];
                const unsigned long long* bp = (const unsigned long long*)&sm.g.sB[kk][4*tc];
                unsigned long long b0 = bp[0], b1 = bp[1];
                unsigned long long a0 = ap[0], a1 = ap[1], a2 = ap[2], a3 = ap[3];
                FMA_X2(ch[0][0], a0, b0, ch[0][0]);
                FMA_X2(ch[0][1], a0, b1, ch[0][1]);
                FMA_X2(ch[1][0], a1, b0, ch[1][0]);
                FMA_X2(ch[1][1], a1, b1, ch[1][1]);
                FMA_X2(ch[2][0], a2, b0, ch[2][0]);
                FMA_X2(ch[2][1], a2, b1, ch[2][1]);
                FMA_X2(ch[3][0], a3, b0, ch[3][0]);
                FMA_X2(ch[3][1], a3, b1, ch[3][1]);
            }
            // Kahan fold, packed; exact subtractions via fma(x, -1, y).
#pragma unroll
            for (int i = 0; i < 4; i++)
#pragma unroll
                for (int p = 0; p < 2; p++) {
                    unsigned long long y, t, tmp;
                    FMA_X2(y, comp[i][p], m1, ch[i][p]);
                    ADD_X2(t, sum[i][p], y);
                    FMA_X2(tmp, sum[i][p], m1, t);
                    FMA_X2(comp[i][p], y, m1, tmp);
                    sum[i][p] = t;
                }
            __syncthreads();
        }

#pragma unroll
        for (int i = 0; i < 4; i++)
#pragma unroll
            for (int p = 0; p < 2; p++) {
                unsigned int ulo, uhi;
                UNPK_X2(ulo, uhi, sum[i][p]);
                sm.g.sL[tr*4 + i][tc*4 + 2*p + 0] = __fadd_rn(__uint_as_float(ulo), bias[tc*4 + 2*p + 0]);
                sm.g.sL[tr*4 + i][tc*4 + 2*p + 1] = __fadd_rn(__uint_as_float(uhi), bias[tc*4 + 2*p + 1]);
            }
        if (tid < 64) sm.g.sCnt[tid] = 0;
        __syncthreads();

        const int g = row0 / NT;

        if (tid < 64) {
            const int r = tid;
            float l1 = -INFINITY, l2 = -INFINITY;
            int   e1 = 0, e2 = 0;
            for (int c = 0; c < 64; c++) {
                float l = sm.g.sL[r][c];
                if (l > l1)      { l2 = l1; e2 = e1; l1 = l; e1 = c; }
                else if (l > l2) { l2 = l;  e2 = c; }
            }
            float s = 0.f, sl = 0.f, sq = 0.f;
            for (int c = 0; c < 64; c++) {
                float l  = sm.g.sL[r][c];
                float ex = expf(__fsub_rn(l, l1));
                s  = __fadd_rn(s, ex);
                sl += l;
                sq = __fmaf_rn(l, l, sq);
                sm.g.sL[r][c] = ex;
            }
            const int row = row0 + r;
            float g1 = __fdiv_rn(1.0f, s);
            float g2 = __fdiv_rn(expf(__fsub_rn(l2, l1)), s);
            d_gate1[row] = g1;
            d_gate2[row] = g2;
            d_e12[row]   = e1 | (e2 << 8);
            sm.g.sInv[r] = g1;
            atomicAdd(&sm.g.sCnt[e1], 1);
            atomicAdd(&sm.g.sCnt[e2], 1);
            float lse = l1 + logf(s);
            sm.g.sZ[r] = sq - 2.f * lse * sl + 64.f * lse * lse;
        }
        __syncthreads();

        if (tid < 64) {
            const int c = tid;
            float cs = 0.f;
            for (int r = 0; r < 64; r++) cs += sm.g.sL[r][c] * sm.g.sInv[r];
            atomicAdd(&d_sumprob[g*64 + c], cs);
            atomicAdd(&d_cnt[g*64 + c], (float)sm.g.sCnt[c]);
        }
        if (tid == 0) {
            float z = 0.f;
            for (int r = 0; r < 64; r++) z += sm.g.sZ[r];
            atomicAdd(&d_zsum, z);
        }
        __syncthreads();
    }

    // signal GEMM completion (gates visible device-wide before counter bump)
    __threadfence();
    if (tid == 0) atomicAdd(&d_gemm_done, 1);

    // =============== phase 2: blocks 0-3 sort their group ===============
    if (blockIdx.x < NG) {
        if (tid == 0) {
            while (atomicAdd(&d_gemm_done, 0) < GEMM_BLOCKS) __nanosleep(128);
        }
        __syncthreads();
        __threadfence();

        const int g = blockIdx.x;
        for (int r = tid; r < NT; r += 256) {
            unsigned int gb = __float_as_uint(d_gate1[g*NT + r]);  // positive: bits monotone
            sm.sk[r] = ((unsigned long long)gb << 32) | (unsigned int)(0xFFFFFFFFu - (unsigned)r);
        }
        __syncthreads();
        for (int k = 2; k <= NT; k <<= 1) {
            for (int j = k >> 1; j > 0; j >>= 1) {
#pragma unroll 1
                for (int i = tid; i < NT; i += 256) {
                    int ixj = i ^ j;
                    if (ixj > i) {
                        unsigned long long a = sm.sk[i], b = sm.sk[ixj];
                        bool desc = ((i & k) == 0);
                        if (desc ? (a < b) : (a > b)) { sm.sk[i] = b; sm.sk[ixj] = a; }
                    }
                }
                __syncthreads();
            }
        }
        for (int r = tid; r < NT; r += 256) {
            int tok = (int)(0xFFFFFFFFu - (unsigned int)(sm.sk[r] & 0xFFFFFFFFull));
            int pk  = d_e12[g*NT + tok];
            d_stok[g*NT + r] = (unsigned short)tok;
            d_se0[g*NT + r]  = (unsigned char)(pk & 0xFF);
            d_se1[g*NT + r]  = (unsigned char)((pk >> 8) & 0xFF);
        }
        __syncthreads();
        __threadfence();
        if (tid == 0) atomicAdd(&d_sort_done, 1);
    }

    // =============== phase 3: capacity positions, 2 (g,e) units per block ===============
    if (tid == 0) {
        while (atomicAdd(&d_sort_done, 0) < NG) __nanosleep(128);
    }
    __syncthreads();
    __threadfence();

    for (int u = blockIdx.x; u < NG*NE; u += GEMM_BLOCKS) {
        const int g = u >> 6;
        const int e = u & 63;

        for (int i = tid; i < NT/4; i += 256) {
            ((uint*)sm.p.s0)[i] = ((const uint*)(d_se0 + g*NT))[i];
            ((uint*)sm.p.s1)[i] = ((const uint*)(d_se1 + g*NT))[i];
        }
        for (int i = tid; i < NT/2; i += 256)
            ((uint*)sm.p.stk)[i] = ((const uint*)(d_stok + g*NT))[i];
        __syncthreads();

        const int w    = tid >> 5;       // 0..7, segment of 512 entries
        const int lane = tid & 31;

        int c0 = 0, c1 = 0;
#pragma unroll
        for (int j = 0; j < 16; j++) {
            c0 += __popc(__ballot_sync(0xFFFFFFFFu, sm.p.s0[w*512 + j*32 + lane] == e));
            c1 += __popc(__ballot_sync(0xFFFFFFFFu, sm.p.s1[w*512 + j*32 + lane] == e));
        }
        if (lane == 0) { sm.p.segc[w] = c0; sm.p.segc[8 + w] = c1; }
        __syncthreads();

        if (tid < 32) {
            int v = (lane < 16) ? sm.p.segc[lane] : 0;
#pragma unroll
            for (int d = 1; d < 16; d <<= 1) {
                int t = __shfl_up_sync(0xFFFFFFFFu, v, d);
                if (lane >= d) v += t;
            }
            if (lane < 16) sm.p.segb[lane] = v - sm.p.segc[lane];   // exclusive
        }
        __syncthreads();

        const unsigned lt = (lane == 0) ? 0u : (0xFFFFFFFFu >> (32 - lane));
        int base0 = sm.p.segb[w];
        int base1 = sm.p.segb[8 + w];
#pragma unroll 1
        for (int j = 0; j < 16; j++) {
            bool m = (sm.p.s0[w*512 + j*32 + lane] == e);
            unsigned bal = __ballot_sync(0xFFFFFFFFu, m);
            if (m) d_pos1[g*NT + sm.p.stk[w*512 + j*32 + lane]] = (short)(base0 + __popc(bal & lt));
            base0 += __popc(bal);
        }
#pragma unroll 1
        for (int j = 0; j < 16; j++) {
            bool m = (sm.p.s1[w*512 + j*32 + lane] == e);
            unsigned bal = __ballot_sync(0xFFFFFFFFu, m);
            if (m) d_pos2[g*NT + sm.p.stk[w*512 + j*32 + lane]] = (short)(base1 + __popc(bal & lt));
            base1 += __popc(bal);
        }
        __syncthreads();
    }
}

// ---------------- sparse scatter: <=4 scattered stores per token ----------------
__global__ void __launch_bounds__(256) sparse_scatter(float* __restrict__ out) {
    const int gt = blockIdx.x * 256 + threadIdx.x;   // grid 64 -> 16384 threads
    const int pk = d_e12[gt];
    const int e1 = pk & 0xFF, e2 = (pk >> 8) & 0xFF;
    const int p1 = d_pos1[gt], p2 = d_pos2[gt];
    if (p1 < CAP) {
        long long b = ((long long)gt * NE + e1) * CAP + p1;
        out[b]        = 1.0f;
        out[GTEC + b] = d_gate1[gt];
    }
    if (p2 < CAP) {
        long long b = ((long long)gt * NE + e2) * CAP + p2;
        out[b]        = 1.0f;
        out[GTEC + b] = d_gate2[gt];
    }
}

// ---------------- losses ----------------
__global__ void finalize(float* __restrict__ out) {
    __shared__ float red[256];
    const int t = threadIdx.x;
    red[t] = d_cnt[t] * d_sumprob[t];   // t in [0,256) == NG*NE
    __syncthreads();
    for (int s = 128; s > 0; s >>= 1) {
        if (t < s) red[t] += red[t + s];
        __syncthreads();
    }
    if (t == 0) {
        out[2*GTEC]     = red[0] * ((float)NE / ((float)NG * (float)NT * (float)NT));
        out[2*GTEC + 1] = d_zsum / (float)((long long)NG * NT * NE);
    }
}

// ---------------- launch ----------------
extern "C" void kernel_launch(void* const* d_in, const int* in_sizes, int n_in,
                              void* d_out, int out_size) {
    const float* A    = (const float*)d_in[0];   // token_inputs [4,4096,2048]
    const float* Wm   = (const float*)d_in[1];   // W [2048,64]
    const float* bias = (const float*)d_in[2];   // b [64]
    float* out = (float*)d_out;

    init_accum<<<1, 256>>>();
    fused_all<<<GEMM_BLOCKS + ZERO_BLOCKS, 256>>>(A, Wm, bias, out);
    sparse_scatter<<<GT/256, 256>>>(out);
    finalize<<<1, 256>>>(out);
}

// round 10
// speedup vs baseline: 1.7080x; 1.7080x over previous
#include <cuda_runtime.h>
#include <math.h>

#define NG   4
#define NT   4096
#define ND   2048
#define NE   64
#define CAP  128
#define GT   (NG*NT)            // 16384
static const long long GTEC = (long long)GT * NE * CAP;   // 134217728

#define GEMM_BLOCKS 256
#define ZERO_BLOCKS 128

// ---------------- scratch (device globals; no allocation) ----------------
__device__ float          d_gate1[GT];
__device__ float          d_gate2[GT];
__device__ int            d_e12[GT];        // e1 | (e2<<8)
__device__ unsigned char  d_se0[GT];        // sorted-order top-1 expert id
__device__ unsigned char  d_se1[GT];        // sorted-order top-2 expert id
__device__ unsigned short d_stok[GT];       // sorted-order token id
__device__ short          d_pos1[GT];       // capacity position of top-1
__device__ short          d_pos2[GT];       // capacity position of top-2
__device__ float          d_sumprob[NG*NE];
__device__ float          d_cnt[NG*NE];
__device__ float          d_zsum;

// ---------------- f32x2 packed helpers ----------------
#define FMA_X2(d,a,b,c) asm("fma.rn.f32x2 %0, %1, %2, %3;" : "=l"(d) : "l"(a), "l"(b), "l"(c))
#define ADD_X2(d,a,b)   asm("add.rn.f32x2 %0, %1, %2;"     : "=l"(d) : "l"(a), "l"(b))
#define UNPK_X2(lo,hi,v) asm("mov.b64 {%0,%1}, %2;" : "=r"(lo), "=r"(hi) : "l"(v))

// ---------------- init accumulators ----------------
__global__ void init_accum() {
    int t = threadIdx.x;
    if (t < NG*NE) { d_sumprob[t] = 0.f; d_cnt[t] = 0.f; }
    if (t == 0) d_zsum = 0.f;
}

// ---------------- fused: GEMM(+softmax/top2/losses) blocks + output-zeroing blocks ----------------
// blocks [0,256): 64 logits rows each. blocks [256,384): stream zeros over out.
// 384 blocks co-resident in one wave: the zero stream (DRAM-write-bound) hides
// the GEMM (FFMA-bound). Proven in R4: this kernel ran ~320us ~= write-only time.
__global__ void __launch_bounds__(256) fused_gemm_zero(
    const float* __restrict__ A,   // [GT][ND]
    const float* __restrict__ Wm,  // [ND][NE]
    const float* __restrict__ bias,// [NE]
    float* __restrict__ out
) {
    // ---------- zero path ----------
    if (blockIdx.x >= GEMM_BLOCKS) {
        const size_t n4 = (size_t)(2 * GTEC) / 4;            // 67108864 float4s
        const size_t stride = (size_t)ZERO_BLOCKS * 256;
        float4* o4 = (float4*)out;
        const float4 z = make_float4(0.f, 0.f, 0.f, 0.f);
        for (size_t i = (size_t)(blockIdx.x - GEMM_BLOCKS) * 256 + threadIdx.x;
             i < n4; i += stride)
            __stwt(o4 + i, z);
        return;
    }

    // ---------- GEMM path ----------
    __shared__ float sA2[32][132];  // duplicated pairs: [kk][2*row .. 2*row+1] = a
    __shared__ float sB[32][64];    // W chunk [kk][e]
    __shared__ float sL[64][65];    // logits tile, then exp() values
    __shared__ float sInv[64];
    __shared__ float sZ[64];
    __shared__ int   sCnt[64];

    const int tid  = threadIdx.x;
    const int row0 = blockIdx.x * 64;
    const int tr   = tid >> 4;     // 0..15, rows 4*tr
    const int tc   = tid & 15;     // 0..15, cols 4*tc

    unsigned long long m1;         // packed (-1,-1)
    asm("mov.b64 %0, {%1,%2};" : "=l"(m1) : "r"(__float_as_uint(-1.0f)), "r"(__float_as_uint(-1.0f)));

    unsigned long long sum[4][2], comp[4][2];
#pragma unroll
    for (int i = 0; i < 4; i++)
#pragma unroll
        for (int p = 0; p < 2; p++) { sum[i][p] = 0ull; comp[i][p] = 0ull; }

    for (int d0 = 0; d0 < ND; d0 += 32) {
#pragma unroll
        for (int it = 0; it < 2; it++) {
            int idx = tid + it * 256;          // 0..511
            int r   = idx >> 3;
            int c4  = (idx & 7) << 2;
            float4 v = *(const float4*)(A + (size_t)(row0 + r) * ND + d0 + c4);
            *(float2*)&sA2[c4+0][2*r] = make_float2(v.x, v.x);
            *(float2*)&sA2[c4+1][2*r] = make_float2(v.y, v.y);
            *(float2*)&sA2[c4+2][2*r] = make_float2(v.z, v.z);
            *(float2*)&sA2[c4+3][2*r] = make_float2(v.w, v.w);
        }
#pragma unroll
        for (int it = 0; it < 2; it++) {
            int idx = tid + it * 256;
            int r   = idx >> 4;
            int c4  = (idx & 15) << 2;
            *(float4*)&sB[r][c4] = *(const float4*)(Wm + (size_t)(d0 + r) * NE + c4);
        }
        __syncthreads();

        unsigned long long ch[4][2];
#pragma unroll
        for (int i = 0; i < 4; i++)
#pragma unroll
            for (int p = 0; p < 2; p++) ch[i][p] = 0ull;

#pragma unroll
        for (int kk = 0; kk < 32; kk++) {
            const unsigned long long* ap =
                (const unsigned long long*)&sA2[kk][8*tr];   // 4 x (a_i,a_i)
            const unsigned long long* bp =
                (const unsigned long long*)&sB[kk][4*tc];    // (b0,b1),(b2,b3)
            unsigned long long b0 = bp[0], b1 = bp[1];
            unsigned long long a0 = ap[0], a1 = ap[1], a2 = ap[2], a3 = ap[3];
            FMA_X2(ch[0][0], a0, b0, ch[0][0]);
            FMA_X2(ch[0][1], a0, b1, ch[0][1]);
            FMA_X2(ch[1][0], a1, b0, ch[1][0]);
            FMA_X2(ch[1][1], a1, b1, ch[1][1]);
            FMA_X2(ch[2][0], a2, b0, ch[2][0]);
            FMA_X2(ch[2][1], a2, b1, ch[2][1]);
            FMA_X2(ch[3][0], a3, b0, ch[3][0]);
            FMA_X2(ch[3][1], a3, b1, ch[3][1]);
        }
        // Kahan fold, packed; exact subtractions via fma(x, -1, y).
#pragma unroll
        for (int i = 0; i < 4; i++)
#pragma unroll
            for (int p = 0; p < 2; p++) {
                unsigned long long y, t, tmp;
                FMA_X2(y, comp[i][p], m1, ch[i][p]);
                ADD_X2(t, sum[i][p], y);
                FMA_X2(tmp, sum[i][p], m1, t);
                FMA_X2(comp[i][p], y, m1, tmp);
                sum[i][p] = t;
            }
        __syncthreads();
    }

#pragma unroll
    for (int i = 0; i < 4; i++)
#pragma unroll
        for (int p = 0; p < 2; p++) {
            unsigned int ulo, uhi;
            UNPK_X2(ulo, uhi, sum[i][p]);
            sL[tr*4 + i][tc*4 + 2*p + 0] = __fadd_rn(__uint_as_float(ulo), bias[tc*4 + 2*p + 0]);
            sL[tr*4 + i][tc*4 + 2*p + 1] = __fadd_rn(__uint_as_float(uhi), bias[tc*4 + 2*p + 1]);
        }
    if (tid < 64) sCnt[tid] = 0;
    __syncthreads();

    const int g = row0 / NT;

    if (tid < 64) {
        const int r = tid;
        float l1 = -INFINITY, l2 = -INFINITY;
        int   e1 = 0, e2 = 0;
        for (int c = 0; c < 64; c++) {
            float l = sL[r][c];
            if (l > l1)      { l2 = l1; e2 = e1; l1 = l; e1 = c; }
            else if (l > l2) { l2 = l;  e2 = c; }
        }
        float s = 0.f, sl = 0.f, sq = 0.f;
        for (int c = 0; c < 64; c++) {
            float l  = sL[r][c];
            float ex = expf(__fsub_rn(l, l1));
            s  = __fadd_rn(s, ex);
            sl += l;
            sq = __fmaf_rn(l, l, sq);
            sL[r][c] = ex;
        }
        const int row = row0 + r;
        float g1 = __fdiv_rn(1.0f, s);
        float g2 = __fdiv_rn(expf(__fsub_rn(l2, l1)), s);
        d_gate1[row] = g1;
        d_gate2[row] = g2;
        d_e12[row]   = e1 | (e2 << 8);
        sInv[r] = g1;
        atomicAdd(&sCnt[e1], 1);
        atomicAdd(&sCnt[e2], 1);
        float lse = l1 + logf(s);
        sZ[r] = sq - 2.f * lse * sl + 64.f * lse * lse;
    }
    __syncthreads();

    if (tid < 64) {
        const int c = tid;
        float cs = 0.f;
        for (int r = 0; r < 64; r++) cs += sL[r][c] * sInv[r];
        atomicAdd(&d_sumprob[g*64 + c], cs);
        atomicAdd(&d_cnt[g*64 + c], (float)sCnt[c]);
    }
    if (tid == 0) {
        float z = 0.f;
        for (int r = 0; r < 64; r++) z += sZ[r];
        atomicAdd(&d_zsum, z);
    }
}

// ---------------- BPR sort: per-group bitonic, descending by gate1 ----------------
__global__ void __launch_bounds__(1024) bpr_sort() {
    __shared__ unsigned long long sk[NT];   // 32 KB
    const int g   = blockIdx.x;
    const int tid = threadIdx.x;
    for (int r = tid; r < NT; r += 1024) {
        unsigned int gb = __float_as_uint(d_gate1[g*NT + r]);  // positive floats: bits monotone
        sk[r] = ((unsigned long long)gb << 32) | (unsigned int)(0xFFFFFFFFu - (unsigned)r);
    }
    __syncthreads();
    for (int k = 2; k <= NT; k <<= 1) {
        for (int j = k >> 1; j > 0; j >>= 1) {
#pragma unroll 1
            for (int i = tid; i < NT; i += 1024) {
                int ixj = i ^ j;
                if (ixj > i) {
                    unsigned long long a = sk[i], b = sk[ixj];
                    bool desc = ((i & k) == 0);
                    if (desc ? (a < b) : (a > b)) { sk[i] = b; sk[ixj] = a; }
                }
            }
            __syncthreads();
        }
    }
    for (int r = tid; r < NT; r += 1024) {
        int tok = (int)(0xFFFFFFFFu - (unsigned int)(sk[r] & 0xFFFFFFFFull));
        int pk  = d_e12[g*NT + tok];
        d_stok[g*NT + r] = (unsigned short)tok;
        d_se0[g*NT + r]  = (unsigned char)(pk & 0xFF);
        d_se1[g*NT + r]  = (unsigned char)((pk >> 8) & 0xFF);
    }
}

// ---------------- capacity positions: grid NG*NE blocks, one (g,e) each ----------------
__global__ void __launch_bounds__(256) compute_pos() {
    __shared__ unsigned char s0[NT];
    __shared__ unsigned char s1[NT];
    __shared__ unsigned short stk[NT];
    __shared__ int segc[16];
    __shared__ int segb[16];

    const int g = blockIdx.x >> 6;
    const int e = blockIdx.x & 63;
    const int tid = threadIdx.x;

    for (int i = tid; i < NT/4; i += 256) {
        ((uint*)s0)[i]  = ((const uint*)(d_se0 + g*NT))[i];
        ((uint*)s1)[i]  = ((const uint*)(d_se1 + g*NT))[i];
    }
    for (int i = tid; i < NT/2; i += 256)
        ((uint*)stk)[i] = ((const uint*)(d_stok + g*NT))[i];
    __syncthreads();

    const int w    = tid >> 5;       // 0..7, segment of 512 entries
    const int lane = tid & 31;

    int c0 = 0, c1 = 0;
#pragma unroll
    for (int j = 0; j < 16; j++) {
        c0 += __popc(__ballot_sync(0xFFFFFFFFu, s0[w*512 + j*32 + lane] == e));
        c1 += __popc(__ballot_sync(0xFFFFFFFFu, s1[w*512 + j*32 + lane] == e));
    }
    if (lane == 0) { segc[w] = c0; segc[8 + w] = c1; }
    __syncthreads();

    if (tid < 32) {
        int v = (lane < 16) ? segc[lane] : 0;
#pragma unroll
        for (int d = 1; d < 16; d <<= 1) {
            int t = __shfl_up_sync(0xFFFFFFFFu, v, d);
            if (lane >= d) v += t;
        }
        if (lane < 16) segb[lane] = v - segc[lane];   // exclusive
    }
    __syncthreads();

    const unsigned lt = (lane == 0) ? 0u : (0xFFFFFFFFu >> (32 - lane));
    int base0 = segb[w];
    int base1 = segb[8 + w];
#pragma unroll 1
    for (int j = 0; j < 16; j++) {
        bool m = (s0[w*512 + j*32 + lane] == e);
        unsigned bal = __ballot_sync(0xFFFFFFFFu, m);
        if (m) d_pos1[g*NT + stk[w*512 + j*32 + lane]] = (short)(base0 + __popc(bal & lt));
        base0 += __popc(bal);
    }
#pragma unroll 1
    for (int j = 0; j < 16; j++) {
        bool m = (s1[w*512 + j*32 + lane] == e);
        unsigned bal = __ballot_sync(0xFFFFFFFFu, m);
        if (m) d_pos2[g*NT + stk[w*512 + j*32 + lane]] = (short)(base1 + __popc(bal & lt));
        base1 += __popc(bal);
    }
}

// ---------------- sparse scatter: <=4 scattered stores per token ----------------
__global__ void __launch_bounds__(256) sparse_scatter(float* __restrict__ out) {
    const int gt = blockIdx.x * 256 + threadIdx.x;   // grid 64 -> 16384 threads
    const int pk = d_e12[gt];
    const int e1 = pk & 0xFF, e2 = (pk >> 8) & 0xFF;
    const int p1 = d_pos1[gt], p2 = d_pos2[gt];
    if (p1 < CAP) {
        long long b = ((long long)gt * NE + e1) * CAP + p1;
        out[b]        = 1.0f;
        out[GTEC + b] = d_gate1[gt];
    }
    if (p2 < CAP) {
        long long b = ((long long)gt * NE + e2) * CAP + p2;
        out[b]        = 1.0f;
        out[GTEC + b] = d_gate2[gt];
    }
}

// ---------------- losses ----------------
__global__ void finalize(float* __restrict__ out) {
    __shared__ float red[256];
    const int t = threadIdx.x;
    red[t] = d_cnt[t] * d_sumprob[t];   // t in [0,256) == NG*NE
    __syncthreads();
    for (int s = 128; s > 0; s >>= 1) {
        if (t < s) red[t] += red[t + s];
        __syncthreads();
    }
    if (t == 0) {
        out[2*GTEC]     = red[0] * ((float)NE / ((float)NG * (float)NT * (float)NT));
        out[2*GTEC + 1] = d_zsum / (float)((long long)NG * NT * NE);
    }
}

// ---------------- launch ----------------
extern "C" void kernel_launch(void* const* d_in, const int* in_sizes, int n_in,
                              void* d_out, int out_size) {
    const float* A    = (const float*)d_in[0];   // token_inputs [4,4096,2048]
    const float* Wm   = (const float*)d_in[1];   // W [2048,64]
    const float* bias = (const float*)d_in[2];   // b [64]
    float* out = (float*)d_out;

    init_accum<<<1, 256>>>();
    fused_gemm_zero<<<GEMM_BLOCKS + ZERO_BLOCKS, 256>>>(A, Wm, bias, out);
    bpr_sort<<<NG, 1024>>>();
    compute_pos<<<NG*NE, 256>>>();
    sparse_scatter<<<GT/256, 256>>>(out);
    finalize<<<1, 256>>>(out);
}

// round 12
// speedup vs baseline: 1.7893x; 1.0476x over previous
#include <cuda_runtime.h>
#include <math.h>

#define NG   4
#define NT   4096
#define ND   2048
#define NE   64
#define CAP  128
#define GT   (NG*NT)            // 16384
static const long long GTEC = (long long)GT * NE * CAP;   // 134217728

#define GEMM_BLOCKS 256
#define ZERO_BLOCKS 128
#define TILE_BYTES  32768                    // one 32 KB bulk store
#define TILES_TOTAL 32768                    // 1.07 GB / 32 KB
#define TILES_PER_BLOCK (TILES_TOTAL / ZERO_BLOCKS)   // 256

// ---------------- scratch (device globals; no allocation) ----------------
__device__ float          d_gate1[GT];
__device__ float          d_gate2[GT];
__device__ int            d_e12[GT];        // e1 | (e2<<8)
__device__ unsigned char  d_se0[GT];        // sorted-order top-1 expert id
__device__ unsigned char  d_se1[GT];        // sorted-order top-2 expert id
__device__ unsigned short d_stok[GT];       // sorted-order token id
__device__ short          d_pos1[GT];       // capacity position of top-1
__device__ short          d_pos2[GT];       // capacity position of top-2
__device__ float          d_sumprob[NG*NE]; // zero-init; reset by finalize for next replay
__device__ float          d_cnt[NG*NE];
__device__ float          d_zsum;

// ---------------- f32x2 packed helpers ----------------
#define FMA_X2(d,a,b,c) asm("fma.rn.f32x2 %0, %1, %2, %3;" : "=l"(d) : "l"(a), "l"(b), "l"(c))
#define ADD_X2(d,a,b)   asm("add.rn.f32x2 %0, %1, %2;"     : "=l"(d) : "l"(a), "l"(b))
#define UNPK_X2(lo,hi,v) asm("mov.b64 {%0,%1}, %2;" : "=r"(lo), "=r"(hi) : "l"(v))

// ---------------- shared memory union (static, 42.5 KB < 48 KB) ----------------
struct GemmSmem {
    float sA2[32][132];
    float sB[32][64];
    float sL[64][65];
    float sInv[64];
    float sZ[64];
    int   sCnt[64];
};
union FusedSmem {
    GemmSmem g;
    float    zb[TILE_BYTES/4];   // 32 KB constant-zero staging buffer
};

// ---------------- fused: GEMM blocks + TMA-bulk zeroing blocks ----------------
// blocks [0,256): 64 logits rows each (FFMA2 + Kahan, bit-identical since R3).
// blocks [256,384): zero a 32 KB smem buffer once, then issue 256 x 32 KB
// cp.async.bulk stores each. Buffer content never changes -> no inter-store
// hazards, full queue depth. R7 measured this store path at ~5.2 TB/s.
__global__ void __launch_bounds__(256) fused_gemm_zero(
    const float* __restrict__ A,   // [GT][ND]
    const float* __restrict__ Wm,  // [ND][NE]
    const float* __restrict__ bias,// [NE]
    float* __restrict__ out
) {
    __shared__ FusedSmem sm;
    const int tid = threadIdx.x;

    // ---------- TMA zero path ----------
    if (blockIdx.x >= GEMM_BLOCKS) {
        for (int i = tid; i < TILE_BYTES/16; i += 256)
            ((float4*)sm.zb)[i] = make_float4(0.f, 0.f, 0.f, 0.f);
        __syncthreads();
        asm volatile("fence.proxy.async.shared::cta;" ::: "memory");
        if (tid == 0) {
            unsigned saddr = (unsigned)__cvta_generic_to_shared(sm.zb);
            char* gbase = (char*)out +
                (long long)(blockIdx.x - GEMM_BLOCKS) * TILES_PER_BLOCK * (long long)TILE_BYTES;
#pragma unroll 4
            for (int t = 0; t < TILES_PER_BLOCK; t++) {
                asm volatile("cp.async.bulk.global.shared::cta.bulk_group [%0], [%1], %2;"
                             :: "l"(gbase + (long long)t * TILE_BYTES),
                                "r"(saddr), "r"((int)TILE_BYTES) : "memory");
            }
            asm volatile("cp.async.bulk.commit_group;" ::: "memory");
            asm volatile("cp.async.bulk.wait_group 0;" ::: "memory");
        }
        return;
    }

    // ---------- GEMM path ----------
    const int row0 = blockIdx.x * 64;
    const int tr   = tid >> 4;     // 0..15, rows 4*tr
    const int tc   = tid & 15;     // 0..15, cols 4*tc

    unsigned long long m1;         // packed (-1,-1)
    asm("mov.b64 %0, {%1,%2};" : "=l"(m1) : "r"(__float_as_uint(-1.0f)), "r"(__float_as_uint(-1.0f)));

    unsigned long long sum[4][2], comp[4][2];
#pragma unroll
    for (int i = 0; i < 4; i++)
#pragma unroll
        for (int p = 0; p < 2; p++) { sum[i][p] = 0ull; comp[i][p] = 0ull; }

    for (int d0 = 0; d0 < ND; d0 += 32) {
#pragma unroll
        for (int it = 0; it < 2; it++) {
            int idx = tid + it * 256;          // 0..511
            int r   = idx >> 3;
            int c4  = (idx & 7) << 2;
            float4 v = *(const float4*)(A + (size_t)(row0 + r) * ND + d0 + c4);
            *(float2*)&sm.g.sA2[c4+0][2*r] = make_float2(v.x, v.x);
            *(float2*)&sm.g.sA2[c4+1][2*r] = make_float2(v.y, v.y);
            *(float2*)&sm.g.sA2[c4+2][2*r] = make_float2(v.z, v.z);
            *(float2*)&sm.g.sA2[c4+3][2*r] = make_float2(v.w, v.w);
        }
#pragma unroll
        for (int it = 0; it < 2; it++) {
            int idx = tid + it * 256;
            int r   = idx >> 4;
            int c4  = (idx & 15) << 2;
            *(float4*)&sm.g.sB[r][c4] = *(const float4*)(Wm + (size_t)(d0 + r) * NE + c4);
        }
        __syncthreads();

        unsigned long long ch[4][2];
#pragma unroll
        for (int i = 0; i < 4; i++)
#pragma unroll
            for (int p = 0; p < 2; p++) ch[i][p] = 0ull;

#pragma unroll
        for (int kk = 0; kk < 32; kk++) {
            const unsigned long long* ap =
                (const unsigned long long*)&sm.g.sA2[kk][8*tr];   // 4 x (a_i,a_i)
            const unsigned long long* bp =
                (const unsigned long long*)&sm.g.sB[kk][4*tc];    // (b0,b1),(b2,b3)
            unsigned long long b0 = bp[0], b1 = bp[1];
            unsigned long long a0 = ap[0], a1 = ap[1], a2 = ap[2], a3 = ap[3];
            FMA_X2(ch[0][0], a0, b0, ch[0][0]);
            FMA_X2(ch[0][1], a0, b1, ch[0][1]);
            FMA_X2(ch[1][0], a1, b0, ch[1][0]);
            FMA_X2(ch[1][1], a1, b1, ch[1][1]);
            FMA_X2(ch[2][0], a2, b0, ch[2][0]);
            FMA_X2(ch[2][1], a2, b1, ch[2][1]);
            FMA_X2(ch[3][0], a3, b0, ch[3][0]);
            FMA_X2(ch[3][1], a3, b1, ch[3][1]);
        }
        // Kahan fold, packed; exact subtractions via fma(x, -1, y).
#pragma unroll
        for (int i = 0; i < 4; i++)
#pragma unroll
            for (int p = 0; p < 2; p++) {
                unsigned long long y, t, tmp;
                FMA_X2(y, comp[i][p], m1, ch[i][p]);
                ADD_X2(t, sum[i][p], y);
                FMA_X2(tmp, sum[i][p], m1, t);
                FMA_X2(comp[i][p], y, m1, tmp);
                sum[i][p] = t;
            }
        __syncthreads();
    }

#pragma unroll
    for (int i = 0; i < 4; i++)
#pragma unroll
        for (int p = 0; p < 2; p++) {
            unsigned int ulo, uhi;
            UNPK_X2(ulo, uhi, sum[i][p]);
            sm.g.sL[tr*4 + i][tc*4 + 2*p + 0] = __fadd_rn(__uint_as_float(ulo), bias[tc*4 + 2*p + 0]);
            sm.g.sL[tr*4 + i][tc*4 + 2*p + 1] = __fadd_rn(__uint_as_float(uhi), bias[tc*4 + 2*p + 1]);
        }
    if (tid < 64) sm.g.sCnt[tid] = 0;
    __syncthreads();

    const int g = row0 / NT;

    if (tid < 64) {
        const int r = tid;
        float l1 = -INFINITY, l2 = -INFINITY;
        int   e1 = 0, e2 = 0;
        for (int c = 0; c < 64; c++) {
            float l = sm.g.sL[r][c];
            if (l > l1)      { l2 = l1; e2 = e1; l1 = l; e1 = c; }
            else if (l > l2) { l2 = l;  e2 = c; }
        }
        float s = 0.f, sl = 0.f, sq = 0.f;
        for (int c = 0; c < 64; c++) {
            float l  = sm.g.sL[r][c];
            float ex = expf(__fsub_rn(l, l1));
            s  = __fadd_rn(s, ex);
            sl += l;
            sq = __fmaf_rn(l, l, sq);
            sm.g.sL[r][c] = ex;
        }
        const int row = row0 + r;
        float g1 = __fdiv_rn(1.0f, s);
        float g2 = __fdiv_rn(expf(__fsub_rn(l2, l1)), s);
        d_gate1[row] = g1;
        d_gate2[row] = g2;
        d_e12[row]   = e1 | (e2 << 8);
        sm.g.sInv[r] = g1;
        atomicAdd(&sm.g.sCnt[e1], 1);
        atomicAdd(&sm.g.sCnt[e2], 1);
        float lse = l1 + logf(s);
        sm.g.sZ[r] = sq - 2.f * lse * sl + 64.f * lse * lse;
    }
    __syncthreads();

    if (tid < 64) {
        const int c = tid;
        float cs = 0.f;
        for (int r = 0; r < 64; r++) cs += sm.g.sL[r][c] * sm.g.sInv[r];
        atomicAdd(&d_sumprob[g*64 + c], cs);
        atomicAdd(&d_cnt[g*64 + c], (float)sm.g.sCnt[c]);
    }
    if (tid == 0) {
        float z = 0.f;
        for (int r = 0; r < 64; r++) z += sm.g.sZ[r];
        atomicAdd(&d_zsum, z);
    }
}

// ---------------- BPR sort: per-group bitonic, descending by gate1 ----------------
__global__ void __launch_bounds__(1024) bpr_sort() {
    __shared__ unsigned long long sk[NT];   // 32 KB
    const int g   = blockIdx.x;
    const int tid = threadIdx.x;
    for (int r = tid; r < NT; r += 1024) {
        unsigned int gb = __float_as_uint(d_gate1[g*NT + r]);  // positive floats: bits monotone
        sk[r] = ((unsigned long long)gb << 32) | (unsigned int)(0xFFFFFFFFu - (unsigned)r);
    }
    __syncthreads();
    for (int k = 2; k <= NT; k <<= 1) {
        for (int j = k >> 1; j > 0; j >>= 1) {
#pragma unroll 1
            for (int i = tid; i < NT; i += 1024) {
                int ixj = i ^ j;
                if (ixj > i) {
                    unsigned long long a = sk[i], b = sk[ixj];
                    bool desc = ((i & k) == 0);
                    if (desc ? (a < b) : (a > b)) { sk[i] = b; sk[ixj] = a; }
                }
            }
            __syncthreads();
        }
    }
    for (int r = tid; r < NT; r += 1024) {
        int tok = (int)(0xFFFFFFFFu - (unsigned int)(sk[r] & 0xFFFFFFFFull));
        int pk  = d_e12[g*NT + tok];
        d_stok[g*NT + r] = (unsigned short)tok;
        d_se0[g*NT + r]  = (unsigned char)(pk & 0xFF);
        d_se1[g*NT + r]  = (unsigned char)((pk >> 8) & 0xFF);
    }
}

// ---------------- capacity positions: grid NG*NE blocks, one (g,e) each ----------------
__global__ void __launch_bounds__(256) compute_pos() {
    __shared__ unsigned char s0[NT];
    __shared__ unsigned char s1[NT];
    __shared__ unsigned short stk[NT];
    __shared__ int segc[16];
    __shared__ int segb[16];

    const int g = blockIdx.x >> 6;
    const int e = blockIdx.x & 63;
    const int tid = threadIdx.x;

    for (int i = tid; i < NT/4; i += 256) {
        ((uint*)s0)[i]  = ((const uint*)(d_se0 + g*NT))[i];
        ((uint*)s1)[i]  = ((const uint*)(d_se1 + g*NT))[i];
    }
    for (int i = tid; i < NT/2; i += 256)
        ((uint*)stk)[i] = ((const uint*)(d_stok + g*NT))[i];
    __syncthreads();

    const int w    = tid >> 5;       // 0..7, segment of 512 entries
    const int lane = tid & 31;

    int c0 = 0, c1 = 0;
#pragma unroll
    for (int j = 0; j < 16; j++) {
        c0 += __popc(__ballot_sync(0xFFFFFFFFu, s0[w*512 + j*32 + lane] == e));
        c1 += __popc(__ballot_sync(0xFFFFFFFFu, s1[w*512 + j*32 + lane] == e));
    }
    if (lane == 0) { segc[w] = c0; segc[8 + w] = c1; }
    __syncthreads();

    if (tid < 32) {
        int v = (lane < 16) ? segc[lane] : 0;
#pragma unroll
        for (int d = 1; d < 16; d <<= 1) {
            int t = __shfl_up_sync(0xFFFFFFFFu, v, d);
            if (lane >= d) v += t;
        }
        if (lane < 16) segb[lane] = v - segc[lane];   // exclusive
    }
    __syncthreads();

    const unsigned lt = (lane == 0) ? 0u : (0xFFFFFFFFu >> (32 - lane));
    int base0 = segb[w];
    int base1 = segb[8 + w];
#pragma unroll 1
    for (int j = 0; j < 16; j++) {
        bool m = (s0[w*512 + j*32 + lane] == e);
        unsigned bal = __ballot_sync(0xFFFFFFFFu, m);
        if (m) d_pos1[g*NT + stk[w*512 + j*32 + lane]] = (short)(base0 + __popc(bal & lt));
        base0 += __popc(bal);
    }
#pragma unroll 1
    for (int j = 0; j < 16; j++) {
        bool m = (s1[w*512 + j*32 + lane] == e);
        unsigned bal = __ballot_sync(0xFFFFFFFFu, m);
        if (m) d_pos2[g*NT + stk[w*512 + j*32 + lane]] = (short)(base1 + __popc(bal & lt));
        base1 += __popc(bal);
    }
}

// ---------------- scatter + losses (merged) ----------------
// blocks [0,64): <=4 scattered stores per token. block 64: losses + reset
// of the cross-replay accumulators (so every graph replay starts from zero).
__global__ void __launch_bounds__(256) scatter_finalize(float* __restrict__ out) {
    if (blockIdx.x < 64) {
        const int gt = blockIdx.x * 256 + threadIdx.x;
        const int pk = d_e12[gt];
        const int e1 = pk & 0xFF, e2 = (pk >> 8) & 0xFF;
        const int p1 = d_pos1[gt], p2 = d_pos2[gt];
        if (p1 < CAP) {
            long long b = ((long long)gt * NE + e1) * CAP + p1;
            out[b]        = 1.0f;
            out[GTEC + b] = d_gate1[gt];
        }
        if (p2 < CAP) {
            long long b = ((long long)gt * NE + e2) * CAP + p2;
            out[b]        = 1.0f;
            out[GTEC + b] = d_gate2[gt];
        }
        return;
    }

    __shared__ float red[256];
    const int t = threadIdx.x;
    red[t] = d_cnt[t] * d_sumprob[t];   // t in [0,256) == NG*NE
    __syncthreads();
    // reset accumulators for the next replay (deterministic across replays)
    d_cnt[t] = 0.f; d_sumprob[t] = 0.f;
    for (int s = 128; s > 0; s >>= 1) {
        if (t < s) red[t] += red[t + s];
        __syncthreads();
    }
    if (t == 0) {
        out[2*GTEC]     = red[0] * ((float)NE / ((float)NG * (float)NT * (float)NT));
        out[2*GTEC + 1] = d_zsum / (float)((long long)NG * NT * NE);
        d_zsum = 0.f;
    }
}

// ---------------- launch ----------------
extern "C" void kernel_launch(void* const* d_in, const int* in_sizes, int n_in,
                              void* d_out, int out_size) {
    const float* A    = (const float*)d_in[0];   // token_inputs [4,4096,2048]
    const float* Wm   = (const float*)d_in[1];   // W [2048,64]
    const float* bias = (const float*)d_in[2];   // b [64]
    float* out = (float*)d_out;

    fused_gemm_zero<<<GEMM_BLOCKS + ZERO_BLOCKS, 256>>>(A, Wm, bias, out);
    bpr_sort<<<NG, 1024>>>();
    compute_pos<<<NG*NE, 256>>>();
    scatter_finalize<<<65, 256>>>(out);
}